// round 4
// baseline (speedup 1.0000x reference)
#include <cuda_runtime.h>
#include <math.h>
#include <stdint.h>

#define BATCH 8
#define TOTAL 21824
#define NCAND 3320
#define DETS  100
#define IMGF  1024.0f
#define STH   0.2f
#define NMST  0.6f
#define MAXC  256   // per-class bucket capacity (mean ~41, unreachable bound)

// ---------------- scratch ----------------
__device__ unsigned long long d_keys[BATCH * TOTAL];
__device__ unsigned long long d_cand[BATCH * NCAND];
__device__ unsigned long long d_sur[BATCH * 80 * DETS];
__device__ int                d_surn[BATCH * 80];

__device__ __forceinline__ float sigf(float x) { return 1.0f / (1.0f + expf(-x)); }

__device__ __forceinline__ float key_score(unsigned long long key) {
    unsigned uo = ~((unsigned)(key >> 32));
    unsigned bits = (uo & 0x80000000u) ? (uo ^ 0x80000000u) : (~uo);
    return __uint_as_float(bits);
}

// ---------------- K1: per-anchor score + argmax -> 64-bit key ----------------
// key = (~orderable(score))<<32 | idx<<7 | label : ascending key == (score desc, idx asc);
// keys globally distinct (idx unique). Matches jax.lax.top_k stable tie order.
__global__ void k_score(const float* __restrict__ logits, const float* __restrict__ ctr) {
    int a = blockIdx.x * blockDim.x + threadIdx.x;
    if (a >= BATCH * TOTAL) return;
    const float4* p = reinterpret_cast<const float4*>(logits) + (size_t)a * 20;
    float best = -1e30f;
    int bi = 0;
#pragma unroll
    for (int i = 0; i < 20; i++) {  // strict > keeps first-max (argmax semantics)
        float4 v = p[i];
        if (v.x > best) { best = v.x; bi = 4 * i + 0; }
        if (v.y > best) { best = v.y; bi = 4 * i + 1; }
        if (v.z > best) { best = v.z; bi = 4 * i + 2; }
        if (v.w > best) { best = v.w; bi = 4 * i + 3; }
    }
    float s = sqrtf(sigf(best) * sigf(ctr[a]));
    float sm = (s > STH) ? s : -1.0f;
    unsigned u = __float_as_uint(sm);
    u ^= (u & 0x80000000u) ? 0xFFFFFFFFu : 0x80000000u;
    int i_loc = a % TOTAL;
    d_keys[a] = ((unsigned long long)(~u) << 32) |
                ((unsigned)(i_loc << 7) | (unsigned)bi);
}

// ---------------- K2: per (batch, level) exact top-k ----------------
// Stage 0: 4-pass radix select on the 32-bit score word. If the k-th boundary
// falls inside a group of identical score words (rare bit-ties), stage 1 runs
// up to 4 more passes on the low word restricted to that group. Exact always.
__global__ __launch_bounds__(1024, 1) void k_select() {
    extern __shared__ unsigned smx[];  // hi[n] then lo[n]
    const int LOFF[5] = {0, 16384, 20480, 21504, 21760};
    const int LN[5]   = {16384, 4096, 1024, 256, 64};
    const int LK[5]   = {1000, 1000, 1000, 256, 64};
    const int LB[5]   = {0, 1000, 2000, 3000, 3256};  // fixed output bases

    int b = blockIdx.x / 5, lvl = blockIdx.x % 5;
    int off = LOFF[lvl], n = LN[lvl], k = LK[lvl], base = LB[lvl];
    int tid = threadIdx.x;
    const unsigned long long* kp = d_keys + b * TOTAL + off;
    unsigned long long* outp = d_cand + b * NCAND + base;

    if (k >= n) {  // levels 3,4: take everything, fixed slots
        for (int i = tid; i < n; i += 1024) outp[i] = kp[i];
        return;
    }

    unsigned* hi = smx;
    unsigned* lo = smx + n;
    for (int i = tid; i < n; i += 1024) {
        unsigned long long key = kp[i];
        hi[i] = (unsigned)(key >> 32);
        lo[i] = (unsigned)key;
    }

    __shared__ unsigned hist[256];
    __shared__ unsigned sh_prefix, sh_PH, sh_PL;
    __shared__ int sh_kneed, sh_state, gcnt;  // state: 0 continue, 1 ties, 2 resolved
    if (tid == 0) { sh_state = 0; gcnt = 0; }
    __syncthreads();

    unsigned prefix = 0, Sword = 0;
    int kneed = k, tie = 0;

    // ---- stage 0: radix on hi ----
    for (int shift = 24; shift >= 0; shift -= 8) {
        for (int i = tid; i < 256; i += 1024) hist[i] = 0;
        __syncthreads();
        unsigned mhi = (shift == 24) ? 0u : (0xFFFFFFFFu << (shift + 8));
        for (int i = tid; i < n; i += 1024) {  // n multiple of 1024
            unsigned h = hi[i];
            bool ok = ((h & mhi) == (prefix & mhi));
            unsigned active = __ballot_sync(0xFFFFFFFFu, ok);
            if (ok) {
                unsigned dgt = (h >> shift) & 255u;
                unsigned peers = __match_any_sync(active, dgt);
                if ((int)(tid & 31) == __ffs(peers) - 1) atomicAdd(&hist[dgt], __popc(peers));
            }
        }
        __syncthreads();
        if (tid < 32) {
            int running = 0, dsel = -1, cumbefore = 0;
#pragma unroll
            for (int c = 0; c < 8; c++) {
                int v = (int)hist[c * 32 + tid];
                int s = v;
#pragma unroll
                for (int o = 1; o < 32; o <<= 1) { int t2 = __shfl_up_sync(0xFFFFFFFFu, s, o); if (tid >= o) s += t2; }
                int total = __shfl_sync(0xFFFFFFFFu, s, 31);
                if (dsel < 0) {
                    unsigned flag = __ballot_sync(0xFFFFFFFFu, running + s >= kneed);
                    if (flag) {
                        int l = __ffs(flag) - 1;
                        dsel = c * 32 + l;
                        cumbefore = running + __shfl_sync(0xFFFFFFFFu, s, l) - __shfl_sync(0xFFFFFFFFu, v, l);
                    }
                }
                running += total;
            }
            if (tid == 0) {
                int cnt_d = (int)hist[dsel];
                int nk = kneed - cumbefore;
                if (cnt_d == nk) {
                    sh_PH = prefix | ((unsigned)dsel << shift) | (shift ? ((1u << shift) - 1u) : 0u);
                    sh_PL = 0xFFFFFFFFu;
                    sh_state = 2;
                } else if (shift == 0) {  // tie group on full score word
                    sh_prefix = prefix | (unsigned)dsel;
                    sh_kneed = nk;
                    sh_state = 1;
                } else {
                    sh_prefix = prefix | ((unsigned)dsel << shift);
                    sh_kneed = nk;
                    sh_state = 0;
                }
            }
        }
        __syncthreads();
        if (sh_state == 2) break;
        if (sh_state == 1) { tie = 1; Sword = sh_prefix; kneed = sh_kneed; break; }
        prefix = sh_prefix;
        kneed = sh_kneed;
    }

    // ---- stage 1 (rare): radix on lo within hi==Sword ----
    if (tie) {
        unsigned prefix2 = 0;
        for (int shift = 24; shift >= 0; shift -= 8) {
            for (int i = tid; i < 256; i += 1024) hist[i] = 0;
            __syncthreads();
            unsigned mhi = (shift == 24) ? 0u : (0xFFFFFFFFu << (shift + 8));
            for (int i = tid; i < n; i += 1024) {
                unsigned l2 = lo[i];
                bool ok = (hi[i] == Sword) && ((l2 & mhi) == (prefix2 & mhi));
                unsigned active = __ballot_sync(0xFFFFFFFFu, ok);
                if (ok) {
                    unsigned dgt = (l2 >> shift) & 255u;
                    unsigned peers = __match_any_sync(active, dgt);
                    if ((int)(tid & 31) == __ffs(peers) - 1) atomicAdd(&hist[dgt], __popc(peers));
                }
            }
            __syncthreads();
            if (tid < 32) {
                int running = 0, dsel = -1, cumbefore = 0;
#pragma unroll
                for (int c = 0; c < 8; c++) {
                    int v = (int)hist[c * 32 + tid];
                    int s = v;
#pragma unroll
                    for (int o = 1; o < 32; o <<= 1) { int t2 = __shfl_up_sync(0xFFFFFFFFu, s, o); if (tid >= o) s += t2; }
                    int total = __shfl_sync(0xFFFFFFFFu, s, 31);
                    if (dsel < 0) {
                        unsigned flag = __ballot_sync(0xFFFFFFFFu, running + s >= kneed);
                        if (flag) {
                            int l = __ffs(flag) - 1;
                            dsel = c * 32 + l;
                            cumbefore = running + __shfl_sync(0xFFFFFFFFu, s, l) - __shfl_sync(0xFFFFFFFFu, v, l);
                        }
                    }
                    running += total;
                }
                if (tid == 0) {
                    int cnt_d = (int)hist[dsel];
                    int nk = kneed - cumbefore;
                    if (cnt_d == nk) {
                        sh_PH = Sword;
                        sh_PL = prefix2 | ((unsigned)dsel << shift) | (shift ? ((1u << shift) - 1u) : 0u);
                        sh_state = 2;
                    } else if (shift == 0) {  // lo unique within group -> cnt_d==nk==1 anyway
                        sh_PH = Sword;
                        sh_PL = prefix2 | (unsigned)dsel;
                        sh_state = 2;
                    } else {
                        sh_prefix = prefix2 | ((unsigned)dsel << shift);
                        sh_kneed = nk;
                        sh_state = 0;
                    }
                }
            }
            __syncthreads();
            if (sh_state == 2) break;
            prefix2 = sh_prefix;
            kneed = sh_kneed;
        }
    }

    unsigned PH = sh_PH, PL = sh_PL;  // exactly k keys have (hi<PH) || (hi==PH && lo<=PL)

    // ---- gather to fixed per-level slots (warp-aggregated shared counter) ----
    for (int i = tid; i < n; i += 1024) {
        unsigned h = hi[i];
        unsigned l2 = lo[i];
        bool sel = (h < PH) || (h == PH && l2 <= PL);
        unsigned bal = __ballot_sync(0xFFFFFFFFu, sel);
        int nb = __popc(bal);
        int leader = __ffs(bal) - 1;
        int wb = 0;
        if (nb && (int)(tid & 31) == leader) wb = atomicAdd(&gcnt, nb);
        wb = __shfl_sync(0xFFFFFFFFu, wb, leader < 0 ? 0 : leader);
        if (sel) outp[wb + __popc(bal & ((1u << (tid & 31)) - 1))] =
                     ((unsigned long long)h << 32) | l2;
    }
}

// ---------------- K3: one warp per (batch,class): gather, sort, NMS, sorted survivors ----
__global__ __launch_bounds__(32) void k_nms(const float* __restrict__ reg,
                                            const float* __restrict__ anchors) {
    int b = blockIdx.x / 80, c = blockIdx.x % 80;
    __shared__ unsigned long long kb[MAXC];
    __shared__ float4 bxs[MAXC];
    __shared__ float  ar[MAXC], sv[MAXC];
    __shared__ unsigned char rm[MAXC];
    int lane = threadIdx.x;

    // gather this class's keys
    int cnt = 0;
    for (int base = 0; base < NCAND; base += 32) {
        int i = base + lane;
        unsigned long long key = 0;
        bool ok = false;
        if (i < NCAND) {
            key = d_cand[b * NCAND + i];
            ok = ((int)(key & 127ULL) == c);
        }
        unsigned bal = __ballot_sync(0xFFFFFFFFu, ok);
        if (ok) {
            int p = cnt + __popc(bal & ((1u << lane) - 1));
            if (p < MAXC) kb[p] = key;
        }
        cnt += __popc(bal);
    }
    if (cnt > MAXC) cnt = MAXC;
    if (cnt == 0) {
        if (lane == 0) d_surn[b * 80 + c] = 0;
        return;
    }

    // warp bitonic sort ascending (== score desc, idx asc)
    int m = 2; while (m < cnt) m <<= 1;
    for (int i = lane; i < m; i += 32) if (i >= cnt) kb[i] = ~0ULL;
    __syncwarp();
    for (int kk = 2; kk <= m; kk <<= 1)
        for (int jj = kk >> 1; jj > 0; jj >>= 1) {
            for (int cc = lane; cc < (m >> 1); cc += 32) {
                int i1 = ((cc & ~(jj - 1)) << 1) | (cc & (jj - 1));
                int l1 = i1 | jj;
                bool up = ((i1 & kk) == 0);
                unsigned long long a2 = kb[i1], d2 = kb[l1];
                if ((a2 > d2) == up) { kb[i1] = d2; kb[l1] = a2; }
            }
            __syncwarp();
        }

    // decode
    for (int i = lane; i < cnt; i += 32) {
        unsigned long long key = kb[i];
        int idx = (int)((key >> 7) & 0x7FFFULL);
        sv[i] = key_score(key);
        rm[i] = 0;
        float4 an = reinterpret_cast<const float4*>(anchors)[idx];
        float cx = (an.x + an.z) * 0.5f, cy = (an.y + an.w) * 0.5f;
        float4 r = reinterpret_cast<const float4*>(reg)[(size_t)b * TOTAL + idx];
        float x1 = fminf(fmaxf(cx - r.x, 0.0f), IMGF);
        float y1 = fminf(fmaxf(cy - r.y, 0.0f), IMGF);
        float x2 = fminf(fmaxf(cx + r.z, 0.0f), IMGF);
        float y2 = fminf(fmaxf(cy + r.w, 0.0f), IMGF);
        bxs[i] = make_float4(x1, y1, x2, y2);
        ar[i] = fmaxf(x2 - x1, 0.0f) * fmaxf(y2 - y1, 0.0f);
    }
    __syncwarp();

    // greedy NMS
    for (int i = 0; i < cnt; i++) {
        if (sv[i] <= STH) break;
        if (rm[i]) continue;
        float4 bi = bxs[i];
        float ai = ar[i];
        for (int j = i + 1 + lane; j < cnt; j += 32) {
            float4 bj = bxs[j];
            float iw = fmaxf(fminf(bi.z, bj.z) - fmaxf(bi.x, bj.x), 0.0f);
            float ih = fmaxf(fminf(bi.w, bj.w) - fmaxf(bi.y, bj.y), 0.0f);
            float inter = iw * ih;
            float iou = inter / fmaxf(ai + ar[j] - inter, 1e-9f);
            if (iou > NMST) rm[j] = 1;
        }
        __syncwarp();
    }

    // sorted survivor list, capped at DETS (beyond-100th of one class can't reach top-100)
    int wcnt = 0;
    for (int base = 0; base < cnt; base += 32) {
        int i = base + lane;
        bool acc = (i < cnt) && (sv[i] > STH) && !rm[i];
        unsigned bal = __ballot_sync(0xFFFFFFFFu, acc);
        int p = wcnt + __popc(bal & ((1u << lane) - 1));
        if (acc && p < DETS) d_sur[(size_t)(b * 80 + c) * DETS + p] = kb[i];
        wcnt += __popc(bal);
    }
    if (lane == 0) d_surn[b * 80 + c] = min(wcnt, DETS);
}

// ---------------- K4: per-batch 80-way merge of sorted lists -> top-100, decode, write ----
__global__ __launch_bounds__(128, 1) void k_out(const float* __restrict__ reg,
                                                const float* __restrict__ anchors,
                                                float* __restrict__ out) {
    __shared__ unsigned long long lists[80 * DETS];
    __shared__ int cnts[80];
    __shared__ unsigned long long win[DETS];
    __shared__ int sh_ns;
    int b = blockIdx.x, tid = threadIdx.x;

    const unsigned long long* src = d_sur + (size_t)b * 80 * DETS;
    for (int i = tid; i < 80 * DETS; i += 128) lists[i] = src[i];
    for (int i = tid; i < 80; i += 128) cnts[i] = d_surn[b * 80 + i];
    __syncthreads();

    if (tid < 32) {  // warp 0: register-resident 80-way merge
        int lane = tid;
        int c0 = lane, c1 = lane + 32, c2 = lane + 64;
        unsigned long long cur0 = (cnts[c0] > 0) ? lists[c0 * DETS] : ~0ULL;
        unsigned long long cur1 = (cnts[c1] > 0) ? lists[c1 * DETS] : ~0ULL;
        unsigned long long cur2 = (c2 < 80 && cnts[c2] > 0) ? lists[c2 * DETS] : ~0ULL;
        int h0 = 1, h1 = 1, h2 = 1;
        int t = 0;
        for (; t < DETS; t++) {
            unsigned long long m = cur0 < cur1 ? cur0 : cur1;
            m = m < cur2 ? m : cur2;
            unsigned long long v = m;
#pragma unroll
            for (int o = 16; o > 0; o >>= 1) {
                unsigned long long w = __shfl_xor_sync(0xFFFFFFFFu, v, o);
                v = (w < v) ? w : v;
            }
            if (v == ~0ULL) break;
            unsigned bal = __ballot_sync(0xFFFFFFFFu, m == v);
            int wl = __ffs(bal) - 1;
            if (lane == wl) {  // keys unique -> single winner
                win[t] = v;
                if (cur0 == v)      { cur0 = (h0 < cnts[c0]) ? lists[c0 * DETS + h0] : ~0ULL; h0++; }
                else if (cur1 == v) { cur1 = (h1 < cnts[c1]) ? lists[c1 * DETS + h1] : ~0ULL; h1++; }
                else                { cur2 = (h2 < cnts[c2]) ? lists[c2 * DETS + h2] : ~0ULL; h2++; }
            }
            __syncwarp();
        }
        if (lane == 0) sh_ns = t;
    }
    __syncthreads();

    int ns = sh_ns;
    for (int t = tid; t < DETS; t += 128) {
        float* ob = out + ((size_t)b * DETS + t) * 4;
        if (t >= ns) {
            ob[0] = 0.0f; ob[1] = 0.0f; ob[2] = 0.0f; ob[3] = 0.0f;
            out[BATCH * DETS * 4 + b * DETS + t] = 0.0f;
            out[BATCH * DETS * 5 + b * DETS + t] = -1.0f;
        } else {
            unsigned long long key = win[t];
            int idx = (int)((key >> 7) & 0x7FFFULL);
            float4 an = reinterpret_cast<const float4*>(anchors)[idx];
            float cx = (an.x + an.z) * 0.5f, cy = (an.y + an.w) * 0.5f;
            float4 r = reinterpret_cast<const float4*>(reg)[(size_t)b * TOTAL + idx];
            float x1 = fminf(fmaxf(cx - r.x, 0.0f), IMGF);
            float y1 = fminf(fmaxf(cy - r.y, 0.0f), IMGF);
            float x2 = fminf(fmaxf(cx + r.z, 0.0f), IMGF);
            float y2 = fminf(fmaxf(cy + r.w, 0.0f), IMGF);
            ob[0] = x1; ob[1] = y1; ob[2] = x2; ob[3] = y2;
            out[BATCH * DETS * 4 + b * DETS + t] = key_score(key);
            out[BATCH * DETS * 5 + b * DETS + t] = (float)(key & 127ULL);
        }
    }
}

// ---------------- launch ----------------
extern "C" void kernel_launch(void* const* d_in, const int* in_sizes, int n_in,
                              void* d_out, int out_size) {
    const float* logits  = (const float*)d_in[0];  // (8, 21824, 80)
    const float* reg     = (const float*)d_in[1];  // (8, 21824, 4)
    const float* ctr     = (const float*)d_in[2];  // (8, 21824, 1)
    const float* anchors = (const float*)d_in[3];  // (21824, 4)
    float* out = (float*)d_out;

    cudaFuncSetAttribute(k_select, cudaFuncAttributeMaxDynamicSharedMemorySize, 131072);

    k_score<<<(BATCH * TOTAL + 255) / 256, 256>>>(logits, ctr);
    k_select<<<BATCH * 5, 1024, 131072>>>();
    k_nms<<<BATCH * 80, 32>>>(reg, anchors);
    k_out<<<BATCH, 128>>>(reg, anchors, out);
}

// round 5
// speedup vs baseline: 1.3245x; 1.3245x over previous
#include <cuda_runtime.h>
#include <math.h>
#include <stdint.h>

#define BATCH 8
#define TOTAL 21824
#define NCAND 3320
#define DETS  100
#define IMGF  1024.0f
#define STH   0.2f
#define NMST  0.6f
#define MAXC  256   // per-class bucket capacity (mean ~41, unreachable bound)
#define SMAXO 8000  // k_out survivor capacity (80*DETS)
#define CMAXO 4096  // k_out contention capacity

// ---------------- scratch ----------------
__device__ unsigned long long d_keys[BATCH * TOTAL];
__device__ unsigned long long d_bucket[BATCH * 80 * MAXC];
__device__ int                d_ccnt[BATCH * 80];
__device__ unsigned long long d_sur[BATCH * 80 * DETS];
__device__ int                d_surn[BATCH * 80];

__device__ __forceinline__ float sigf(float x) { return 1.0f / (1.0f + expf(-x)); }

__device__ __forceinline__ float key_score(unsigned long long key) {
    unsigned uo = ~((unsigned)(key >> 32));
    unsigned bits = (uo & 0x80000000u) ? (uo ^ 0x80000000u) : (~uo);
    return __uint_as_float(bits);
}

__device__ __forceinline__ void bucket_push(int b, unsigned long long key) {
    int c = (int)(key & 127ULL);
    int pos = atomicAdd(&d_ccnt[b * 80 + c], 1);
    if (pos < MAXC) d_bucket[(size_t)(b * 80 + c) * MAXC + pos] = key;
}

// ---------------- K1: per-anchor score + argmax -> 64-bit key ----------------
// key = (~orderable(score))<<32 | idx<<7 | label : ascending == (score desc, idx asc);
// keys globally distinct. Matches jax.lax.top_k stable tie order.
__global__ void k_score(const float* __restrict__ logits, const float* __restrict__ ctr) {
    if (blockIdx.x == 0) {
        for (int i = threadIdx.x; i < BATCH * 80; i += 256) d_ccnt[i] = 0;
    }
    int a = blockIdx.x * blockDim.x + threadIdx.x;
    if (a >= BATCH * TOTAL) return;
    const float4* p = reinterpret_cast<const float4*>(logits) + (size_t)a * 20;
    float best = -1e30f;
    int bi = 0;
#pragma unroll
    for (int i = 0; i < 20; i++) {  // strict > keeps first-max (argmax semantics)
        float4 v = p[i];
        if (v.x > best) { best = v.x; bi = 4 * i + 0; }
        if (v.y > best) { best = v.y; bi = 4 * i + 1; }
        if (v.z > best) { best = v.z; bi = 4 * i + 2; }
        if (v.w > best) { best = v.w; bi = 4 * i + 3; }
    }
    float s = sqrtf(sigf(best) * sigf(ctr[a]));
    float sm = (s > STH) ? s : -1.0f;
    unsigned u = __float_as_uint(sm);
    u ^= (u & 0x80000000u) ? 0xFFFFFFFFu : 0x80000000u;
    int i_loc = a % TOTAL;
    d_keys[a] = ((unsigned long long)(~u) << 32) |
                ((unsigned)(i_loc << 7) | (unsigned)bi);
}

// ---------------- K2: per (batch, level) exact top-k -> class-bucket scatter ----------
__global__ __launch_bounds__(1024, 1) void k_select() {
    extern __shared__ unsigned smx[];  // hi[n] then lo[n]
    const int LOFF[5] = {0, 16384, 20480, 21504, 21760};
    const int LN[5]   = {16384, 4096, 1024, 256, 64};
    const int LK[5]   = {1000, 1000, 1000, 256, 64};

    int b = blockIdx.x / 5, lvl = blockIdx.x % 5;
    int off = LOFF[lvl], n = LN[lvl], k = LK[lvl];
    int tid = threadIdx.x;
    const unsigned long long* kp = d_keys + b * TOTAL + off;

    if (k >= n) {  // levels 3,4: everything is selected
        for (int i = tid; i < n; i += 1024) bucket_push(b, kp[i]);
        return;
    }

    unsigned* hi = smx;
    unsigned* lo = smx + n;
    for (int i = tid; i < n; i += 1024) {
        unsigned long long key = kp[i];
        hi[i] = (unsigned)(key >> 32);
        lo[i] = (unsigned)key;
    }

    __shared__ unsigned hist[256];
    __shared__ unsigned sh_prefix, sh_PH, sh_PL;
    __shared__ int sh_kneed, sh_state;
    if (tid == 0) sh_state = 0;
    __syncthreads();

    unsigned prefix = 0, Sword = 0;
    int kneed = k, tie = 0;

    // ---- stage 0: radix on hi (score word) ----
    for (int shift = 24; shift >= 0; shift -= 8) {
        for (int i = tid; i < 256; i += 1024) hist[i] = 0;
        __syncthreads();
        unsigned mhi = (shift == 24) ? 0u : (0xFFFFFFFFu << (shift + 8));
        for (int i = tid; i < n; i += 1024) {  // n multiple of 1024
            unsigned h = hi[i];
            bool ok = ((h & mhi) == (prefix & mhi));
            unsigned active = __ballot_sync(0xFFFFFFFFu, ok);
            if (ok) {
                unsigned dgt = (h >> shift) & 255u;
                unsigned peers = __match_any_sync(active, dgt);
                if ((int)(tid & 31) == __ffs(peers) - 1) atomicAdd(&hist[dgt], __popc(peers));
            }
        }
        __syncthreads();
        if (tid < 32) {
            int running = 0, dsel = -1, cumbefore = 0;
#pragma unroll
            for (int c = 0; c < 8; c++) {
                int v = (int)hist[c * 32 + tid];
                int s = v;
#pragma unroll
                for (int o = 1; o < 32; o <<= 1) { int t2 = __shfl_up_sync(0xFFFFFFFFu, s, o); if (tid >= o) s += t2; }
                int total = __shfl_sync(0xFFFFFFFFu, s, 31);
                if (dsel < 0) {
                    unsigned flag = __ballot_sync(0xFFFFFFFFu, running + s >= kneed);
                    if (flag) {
                        int l = __ffs(flag) - 1;
                        dsel = c * 32 + l;
                        cumbefore = running + __shfl_sync(0xFFFFFFFFu, s, l) - __shfl_sync(0xFFFFFFFFu, v, l);
                    }
                }
                running += total;
            }
            if (tid == 0) {
                int cnt_d = (int)hist[dsel];
                int nk = kneed - cumbefore;
                if (cnt_d == nk) {
                    sh_PH = prefix | ((unsigned)dsel << shift) | (shift ? ((1u << shift) - 1u) : 0u);
                    sh_PL = 0xFFFFFFFFu;
                    sh_state = 2;
                } else if (shift == 0) {  // exact-score-word tie group
                    sh_prefix = prefix | (unsigned)dsel;
                    sh_kneed = nk;
                    sh_state = 1;
                } else {
                    sh_prefix = prefix | ((unsigned)dsel << shift);
                    sh_kneed = nk;
                    sh_state = 0;
                }
            }
        }
        __syncthreads();
        if (sh_state == 2) break;
        if (sh_state == 1) { tie = 1; Sword = sh_prefix; kneed = sh_kneed; break; }
        prefix = sh_prefix;
        kneed = sh_kneed;
    }

    // ---- stage 1 (rare): radix on lo within hi==Sword ----
    if (tie) {
        unsigned prefix2 = 0;
        for (int shift = 24; shift >= 0; shift -= 8) {
            for (int i = tid; i < 256; i += 1024) hist[i] = 0;
            __syncthreads();
            unsigned mhi = (shift == 24) ? 0u : (0xFFFFFFFFu << (shift + 8));
            for (int i = tid; i < n; i += 1024) {
                unsigned l2 = lo[i];
                bool ok = (hi[i] == Sword) && ((l2 & mhi) == (prefix2 & mhi));
                unsigned active = __ballot_sync(0xFFFFFFFFu, ok);
                if (ok) {
                    unsigned dgt = (l2 >> shift) & 255u;
                    unsigned peers = __match_any_sync(active, dgt);
                    if ((int)(tid & 31) == __ffs(peers) - 1) atomicAdd(&hist[dgt], __popc(peers));
                }
            }
            __syncthreads();
            if (tid < 32) {
                int running = 0, dsel = -1, cumbefore = 0;
#pragma unroll
                for (int c = 0; c < 8; c++) {
                    int v = (int)hist[c * 32 + tid];
                    int s = v;
#pragma unroll
                    for (int o = 1; o < 32; o <<= 1) { int t2 = __shfl_up_sync(0xFFFFFFFFu, s, o); if (tid >= o) s += t2; }
                    int total = __shfl_sync(0xFFFFFFFFu, s, 31);
                    if (dsel < 0) {
                        unsigned flag = __ballot_sync(0xFFFFFFFFu, running + s >= kneed);
                        if (flag) {
                            int l = __ffs(flag) - 1;
                            dsel = c * 32 + l;
                            cumbefore = running + __shfl_sync(0xFFFFFFFFu, s, l) - __shfl_sync(0xFFFFFFFFu, v, l);
                        }
                    }
                    running += total;
                }
                if (tid == 0) {
                    int cnt_d = (int)hist[dsel];
                    int nk = kneed - cumbefore;
                    if (cnt_d == nk || shift == 0) {
                        sh_PH = Sword;
                        sh_PL = prefix2 | ((unsigned)dsel << shift) |
                                ((cnt_d == nk && shift) ? ((1u << shift) - 1u) : 0u);
                        sh_state = 2;
                    } else {
                        sh_prefix = prefix2 | ((unsigned)dsel << shift);
                        sh_kneed = nk;
                        sh_state = 0;
                    }
                }
            }
            __syncthreads();
            if (sh_state == 2) break;
            prefix2 = sh_prefix;
            kneed = sh_kneed;
        }
    }

    unsigned PH = sh_PH, PL = sh_PL;  // exactly k keys: (hi<PH) || (hi==PH && lo<=PL)

    // ---- scatter selected keys straight into (batch, class) buckets ----
    for (int i = tid; i < n; i += 1024) {
        unsigned h = hi[i];
        unsigned l2 = lo[i];
        if ((h < PH) || (h == PH && l2 <= PL))
            bucket_push(b, ((unsigned long long)h << 32) | l2);
    }
}

// ---------------- K3: one warp per (batch,class): sort bucket, NMS, sorted survivors ----
__global__ __launch_bounds__(32) void k_nms(const float* __restrict__ reg,
                                            const float* __restrict__ anchors) {
    int bc = blockIdx.x, b = bc / 80;
    __shared__ unsigned long long kb[MAXC];
    __shared__ float4 bxs[MAXC];
    __shared__ float  ar[MAXC], sv[MAXC];
    __shared__ unsigned char rm[MAXC];
    int lane = threadIdx.x;

    int cnt = min(d_ccnt[bc], MAXC);
    if (cnt == 0) {
        if (lane == 0) d_surn[bc] = 0;
        return;
    }
    for (int i = lane; i < cnt; i += 32)
        kb[i] = d_bucket[(size_t)bc * MAXC + i];
    __syncwarp();

    // warp bitonic sort ascending (== score desc, idx asc)
    int m = 2; while (m < cnt) m <<= 1;
    for (int i = lane; i < m; i += 32) if (i >= cnt) kb[i] = ~0ULL;
    __syncwarp();
    for (int kk = 2; kk <= m; kk <<= 1)
        for (int jj = kk >> 1; jj > 0; jj >>= 1) {
            for (int cc = lane; cc < (m >> 1); cc += 32) {
                int i1 = ((cc & ~(jj - 1)) << 1) | (cc & (jj - 1));
                int l1 = i1 | jj;
                bool up = ((i1 & kk) == 0);
                unsigned long long a2 = kb[i1], d2 = kb[l1];
                if ((a2 > d2) == up) { kb[i1] = d2; kb[l1] = a2; }
            }
            __syncwarp();
        }

    // decode
    for (int i = lane; i < cnt; i += 32) {
        unsigned long long key = kb[i];
        int idx = (int)((key >> 7) & 0x7FFFULL);
        sv[i] = key_score(key);
        rm[i] = 0;
        float4 an = reinterpret_cast<const float4*>(anchors)[idx];
        float cx = (an.x + an.z) * 0.5f, cy = (an.y + an.w) * 0.5f;
        float4 r = reinterpret_cast<const float4*>(reg)[(size_t)b * TOTAL + idx];
        float x1 = fminf(fmaxf(cx - r.x, 0.0f), IMGF);
        float y1 = fminf(fmaxf(cy - r.y, 0.0f), IMGF);
        float x2 = fminf(fmaxf(cx + r.z, 0.0f), IMGF);
        float y2 = fminf(fmaxf(cy + r.w, 0.0f), IMGF);
        bxs[i] = make_float4(x1, y1, x2, y2);
        ar[i] = fmaxf(x2 - x1, 0.0f) * fmaxf(y2 - y1, 0.0f);
    }
    __syncwarp();

    // greedy NMS (masked scores sort last; suppressed boxes never suppress)
    for (int i = 0; i < cnt; i++) {
        if (sv[i] <= STH) break;
        if (rm[i]) continue;
        float4 bi = bxs[i];
        float ai = ar[i];
        for (int j = i + 1 + lane; j < cnt; j += 32) {
            float4 bj = bxs[j];
            float iw = fmaxf(fminf(bi.z, bj.z) - fmaxf(bi.x, bj.x), 0.0f);
            float ih = fmaxf(fminf(bi.w, bj.w) - fmaxf(bi.y, bj.y), 0.0f);
            float inter = iw * ih;
            float iou = inter / fmaxf(ai + ar[j] - inter, 1e-9f);
            if (iou > NMST) rm[j] = 1;
        }
        __syncwarp();
    }

    // sorted survivors, capped at DETS (rank-100+ within a class can't reach top-100)
    int wcnt = 0;
    for (int base = 0; base < cnt; base += 32) {
        int i = base + lane;
        bool acc = (i < cnt) && (sv[i] > STH) && !rm[i];
        unsigned bal = __ballot_sync(0xFFFFFFFFu, acc);
        int p = wcnt + __popc(bal & ((1u << lane) - 1));
        if (acc && p < DETS) d_sur[(size_t)bc * DETS + p] = kb[i];
        wcnt += __popc(bal);
    }
    if (lane == 0) d_surn[bc] = min(wcnt, DETS);
}

// ---------------- K4: per-batch top-100 by 2-level histogram + count-rank ----------------
__global__ __launch_bounds__(1024, 1) void k_out(const float* __restrict__ reg,
                                                 const float* __restrict__ anchors,
                                                 float* __restrict__ out) {
    extern __shared__ unsigned long long dynsm[];
    unsigned long long* skeys = dynsm;          // [SMAXO]
    unsigned long long* cont  = dynsm + SMAXO;  // [CMAXO]
    __shared__ int ofs[81];
    __shared__ unsigned hist[256];
    __shared__ int sh_cb, sh_before, ccnt;
    __shared__ unsigned long long win[DETS];

    int b = blockIdx.x, tid = threadIdx.x, lane = tid & 31;

    if (tid < 32) {  // exclusive prefix over 80 class survivor counts
        int runTot = 0;
#pragma unroll
        for (int c = 0; c < 3; c++) {
            int i = c * 32 + lane;
            int v = (i < 80) ? d_surn[b * 80 + i] : 0;
            int s = v;
#pragma unroll
            for (int o = 1; o < 32; o <<= 1) { int t = __shfl_up_sync(0xFFFFFFFFu, s, o); if (lane >= o) s += t; }
            if (i < 80) ofs[i] = runTot + s - v;
            runTot += __shfl_sync(0xFFFFFFFFu, s, 31);
        }
        if (lane == 0) ofs[80] = runTot;
    }
    if (tid == 0) ccnt = 0;
    __syncthreads();

    int S = ofs[80];
    int ns = min(DETS, S);

    // compact survivors: skeys[0..S)
    for (int i = tid; i < 80 * DETS; i += 1024) {
        int c = i / DETS, j = i % DETS;
        int base = ofs[c], cnt = ofs[c + 1] - base;
        if (j < cnt) skeys[base + j] = d_sur[(size_t)(b * 80 + c) * DETS + j];
    }
    __syncthreads();

    if (ns > 0) {
        // pass 1: histogram of bits[56:64)
        for (int i = tid; i < 256; i += 1024) hist[i] = 0;
        __syncthreads();
        for (int i = tid; i < S; i += 1024) atomicAdd(&hist[(unsigned)(skeys[i] >> 56)], 1u);
        __syncthreads();
        if (tid < 32) {
            int running = 0, dsel = -1, cumbefore = 0;
#pragma unroll
            for (int c = 0; c < 8; c++) {
                int v = (int)hist[c * 32 + lane];
                int s = v;
#pragma unroll
                for (int o = 1; o < 32; o <<= 1) { int t = __shfl_up_sync(0xFFFFFFFFu, s, o); if (lane >= o) s += t; }
                int total = __shfl_sync(0xFFFFFFFFu, s, 31);
                if (dsel < 0) {
                    unsigned flag = __ballot_sync(0xFFFFFFFFu, running + s >= ns);
                    if (flag) {
                        int l = __ffs(flag) - 1;
                        dsel = c * 32 + l;
                        cumbefore = running + __shfl_sync(0xFFFFFFFFu, s, l) - __shfl_sync(0xFFFFFFFFu, v, l);
                    }
                }
                running += total;
            }
            if (lane == 0) { sh_cb = dsel; sh_before = cumbefore; }
        }
        __syncthreads();
        int cb0 = sh_cb, kneed1 = ns - sh_before;

        // pass 2: histogram of bits[48:56) within cutoff bucket cb0
        for (int i = tid; i < 256; i += 1024) hist[i] = 0;
        __syncthreads();
        for (int i = tid; i < S; i += 1024) {
            unsigned long long key = skeys[i];
            if ((int)(key >> 56) == cb0) atomicAdd(&hist[(unsigned)(key >> 48) & 255u], 1u);
        }
        __syncthreads();
        if (tid < 32) {
            int running = 0, dsel = -1;
#pragma unroll
            for (int c = 0; c < 8; c++) {
                int v = (int)hist[c * 32 + lane];
                int s = v;
#pragma unroll
                for (int o = 1; o < 32; o <<= 1) { int t = __shfl_up_sync(0xFFFFFFFFu, s, o); if (lane >= o) s += t; }
                int total = __shfl_sync(0xFFFFFFFFu, s, 31);
                if (dsel < 0) {
                    unsigned flag = __ballot_sync(0xFFFFFFFFu, running + s >= kneed1);
                    if (flag) dsel = c * 32 + (__ffs(flag) - 1);
                }
                running += total;
            }
            if (lane == 0) sh_cb = dsel;
        }
        __syncthreads();
        int cb1 = sh_cb;

        // contention set = all keys that can possibly be in the global top-ns
        for (int i = tid; i < S; i += 1024) {
            unsigned long long key = skeys[i];
            int b0 = (int)(key >> 56);
            int b1 = (int)((key >> 48) & 255ULL);
            if (b0 < cb0 || (b0 == cb0 && b1 <= cb1)) {
                int p = atomicAdd(&ccnt, 1);
                if (p < CMAXO) cont[p] = key;
            }
        }
        __syncthreads();
        int C = min(ccnt, CMAXO);

        // exact rank within contention == global rank (all outside keys are larger)
        for (int t = tid; t < C; t += 1024) {
            unsigned long long mk = cont[t];
            int r = 0;
            for (int q = 0; q < C; q++) r += (cont[q] < mk);
            if (r < ns) win[r] = mk;
        }
    }
    __syncthreads();

    // decode + write
    for (int t = tid; t < DETS; t += 1024) {
        float* ob = out + ((size_t)b * DETS + t) * 4;
        if (t >= ns) {
            ob[0] = 0.0f; ob[1] = 0.0f; ob[2] = 0.0f; ob[3] = 0.0f;
            out[BATCH * DETS * 4 + b * DETS + t] = 0.0f;
            out[BATCH * DETS * 5 + b * DETS + t] = -1.0f;
        } else {
            unsigned long long key = win[t];
            int idx = (int)((key >> 7) & 0x7FFFULL);
            float4 an = reinterpret_cast<const float4*>(anchors)[idx];
            float cx = (an.x + an.z) * 0.5f, cy = (an.y + an.w) * 0.5f;
            float4 r = reinterpret_cast<const float4*>(reg)[(size_t)b * TOTAL + idx];
            float x1 = fminf(fmaxf(cx - r.x, 0.0f), IMGF);
            float y1 = fminf(fmaxf(cy - r.y, 0.0f), IMGF);
            float x2 = fminf(fmaxf(cx + r.z, 0.0f), IMGF);
            float y2 = fminf(fmaxf(cy + r.w, 0.0f), IMGF);
            ob[0] = x1; ob[1] = y1; ob[2] = x2; ob[3] = y2;
            out[BATCH * DETS * 4 + b * DETS + t] = key_score(key);
            out[BATCH * DETS * 5 + b * DETS + t] = (float)(key & 127ULL);
        }
    }
}

// ---------------- launch ----------------
extern "C" void kernel_launch(void* const* d_in, const int* in_sizes, int n_in,
                              void* d_out, int out_size) {
    const float* logits  = (const float*)d_in[0];  // (8, 21824, 80)
    const float* reg     = (const float*)d_in[1];  // (8, 21824, 4)
    const float* ctr     = (const float*)d_in[2];  // (8, 21824, 1)
    const float* anchors = (const float*)d_in[3];  // (21824, 4)
    float* out = (float*)d_out;

    cudaFuncSetAttribute(k_select, cudaFuncAttributeMaxDynamicSharedMemorySize, 131072);
    cudaFuncSetAttribute(k_out, cudaFuncAttributeMaxDynamicSharedMemorySize,
                         (SMAXO + CMAXO) * 8);

    k_score<<<(BATCH * TOTAL + 255) / 256, 256>>>(logits, ctr);
    k_select<<<BATCH * 5, 1024, 131072>>>();
    k_nms<<<BATCH * 80, 32>>>(reg, anchors);
    k_out<<<BATCH, 1024, (SMAXO + CMAXO) * 8>>>(reg, anchors, out);
}